// round 15
// baseline (speedup 1.0000x reference)
#include <cuda_runtime.h>
#include <cstdint>

#define B_  2
#define S_  2048
#define D_  512
#define H_  8
#define DH_ 64

// ---- scratch (allocation-free: __device__ globals) ----
__device__ float g_Q [(size_t)B_ * H_ * S_ * DH_];   // [B][H][S][DH]   8 MB
__device__ float g_Kt[(size_t)B_ * H_ * DH_ * S_];   // [B][H][DH][S]   8 MB
__device__ float g_V [(size_t)B_ * S_ * DH_];        // [B][S][DH]      1 MB
__device__ float g_heads[(size_t)B_ * S_ * D_];      // [B][S][D]       8 MB

#define MODE_Q   0
#define MODE_K   1
#define MODE_V   2
#define MODE_OUT 3

// ---- packed fp32x2 helpers (sm_10x) ----
__device__ __forceinline__ void fma2(unsigned long long& d,
                                     unsigned long long a,
                                     unsigned long long b) {
    asm("fma.rn.f32x2 %0, %1, %2, %0;" : "+l"(d) : "l"(a), "l"(b));
}
__device__ __forceinline__ unsigned long long pack2(float x, float y) {
    unsigned long long r;
    asm("mov.b64 %0, {%1, %2};" : "=l"(r) : "f"(x), "f"(y));
    return r;
}
__device__ __forceinline__ float2 unpack2(unsigned long long v) {
    float2 r;
    asm("mov.b64 {%0, %1}, %2;" : "=f"(r.x), "=f"(r.y) : "l"(v));
    return r;
}

// ------------------------------------------------------------------
// GEMM tile body: C = A[M x K] @ W[K x N] + bias, scatter per mode.
// BM=128, BN=64, BK=16, 256 threads, 8x4 microtile, f32x2 FMA.
// A staged in smem PRE-DUPLICATED (pack2(a,a)).
// DOUBLE-BUFFERED: tile t+1 LDGs issue before tile t compute; one
// __syncthreads() per tile. Per kk: 16 FFMA2 + 5 LDS.128 = 32 MACs.
// ------------------------------------------------------------------
__device__ __forceinline__ void gemm_tile(
    const float* __restrict__ A, const float* __restrict__ W,
    const float* __restrict__ bias, float* __restrict__ out,
    int K, int N, int mode, int bxm, int bxn)
{
    __shared__ unsigned long long As2[2][16][128];  // [buf][kk][m] = pack2(a,a) (32 KB)
    __shared__ float Bs[2][16][64];                 // [buf][kk][n]              (8 KB)

    int t  = threadIdx.x;
    int bm = bxm * 128;
    int bn = bxn * 64;
    int tm = (t >> 4) * 8;        // 16 groups x 8 rows = 128
    int tn = (t & 15) * 4;

    int am = t >> 1;              // A-load: row within tile (0..127)
    int aq = (t & 1) * 8;         // A-load: col (k) start (0 or 8)
    int bk = t >> 4;              // B-load: k within tile
    int bn4 = (t & 15) * 4;       // B-load: n start

    const float* Arow = &A[(size_t)(bm + am) * K + aq];
    const float* Wrow = &W[(size_t)bk * N + bn + bn4];

    unsigned long long acc2[8][2] = {};   // [row i][n-pair]

    // prologue: stage tile 0 into buffer 0
    {
        float4 av0 = *(const float4*)&Arow[0];
        float4 av1 = *(const float4*)&Arow[4];
        float4 bv  = *(const float4*)&Wrow[0];
        As2[0][aq + 0][am] = pack2(av0.x, av0.x);
        As2[0][aq + 1][am] = pack2(av0.y, av0.y);
        As2[0][aq + 2][am] = pack2(av0.z, av0.z);
        As2[0][aq + 3][am] = pack2(av0.w, av0.w);
        As2[0][aq + 4][am] = pack2(av1.x, av1.x);
        As2[0][aq + 5][am] = pack2(av1.y, av1.y);
        As2[0][aq + 6][am] = pack2(av1.z, av1.z);
        As2[0][aq + 7][am] = pack2(av1.w, av1.w);
        *(float4*)&Bs[0][bk][bn4] = bv;
    }
    __syncthreads();

    int cur = 0;
    for (int k0 = 16; k0 < K; k0 += 16, cur ^= 1) {
        // issue next tile's global loads FIRST (overlap with compute below)
        float4 av0 = *(const float4*)&Arow[k0];
        float4 av1 = *(const float4*)&Arow[k0 + 4];
        float4 bv  = *(const float4*)&Wrow[(size_t)k0 * N];

        // compute current tile
        #pragma unroll
        for (int kk = 0; kk < 16; kk++) {
            ulonglong2 a01 = *(const ulonglong2*)&As2[cur][kk][tm];
            ulonglong2 a23 = *(const ulonglong2*)&As2[cur][kk][tm + 2];
            ulonglong2 a45 = *(const ulonglong2*)&As2[cur][kk][tm + 4];
            ulonglong2 a67 = *(const ulonglong2*)&As2[cur][kk][tm + 6];
            ulonglong2 b2  = *(const ulonglong2*)&Bs[cur][kk][tn];
            fma2(acc2[0][0], a01.x, b2.x); fma2(acc2[0][1], a01.x, b2.y);
            fma2(acc2[1][0], a01.y, b2.x); fma2(acc2[1][1], a01.y, b2.y);
            fma2(acc2[2][0], a23.x, b2.x); fma2(acc2[2][1], a23.x, b2.y);
            fma2(acc2[3][0], a23.y, b2.x); fma2(acc2[3][1], a23.y, b2.y);
            fma2(acc2[4][0], a45.x, b2.x); fma2(acc2[4][1], a45.x, b2.y);
            fma2(acc2[5][0], a45.y, b2.x); fma2(acc2[5][1], a45.y, b2.y);
            fma2(acc2[6][0], a67.x, b2.x); fma2(acc2[6][1], a67.x, b2.y);
            fma2(acc2[7][0], a67.y, b2.x); fma2(acc2[7][1], a67.y, b2.y);
        }

        // stage next tile into the other buffer (no one reads it until after sync)
        int nxt = cur ^ 1;
        As2[nxt][aq + 0][am] = pack2(av0.x, av0.x);
        As2[nxt][aq + 1][am] = pack2(av0.y, av0.y);
        As2[nxt][aq + 2][am] = pack2(av0.z, av0.z);
        As2[nxt][aq + 3][am] = pack2(av0.w, av0.w);
        As2[nxt][aq + 4][am] = pack2(av1.x, av1.x);
        As2[nxt][aq + 5][am] = pack2(av1.y, av1.y);
        As2[nxt][aq + 6][am] = pack2(av1.z, av1.z);
        As2[nxt][aq + 7][am] = pack2(av1.w, av1.w);
        *(float4*)&Bs[nxt][bk][bn4] = bv;
        __syncthreads();
    }

    // epilogue: compute last tile
    #pragma unroll
    for (int kk = 0; kk < 16; kk++) {
        ulonglong2 a01 = *(const ulonglong2*)&As2[cur][kk][tm];
        ulonglong2 a23 = *(const ulonglong2*)&As2[cur][kk][tm + 2];
        ulonglong2 a45 = *(const ulonglong2*)&As2[cur][kk][tm + 4];
        ulonglong2 a67 = *(const ulonglong2*)&As2[cur][kk][tm + 6];
        ulonglong2 b2  = *(const ulonglong2*)&Bs[cur][kk][tn];
        fma2(acc2[0][0], a01.x, b2.x); fma2(acc2[0][1], a01.x, b2.y);
        fma2(acc2[1][0], a01.y, b2.x); fma2(acc2[1][1], a01.y, b2.y);
        fma2(acc2[2][0], a23.x, b2.x); fma2(acc2[2][1], a23.x, b2.y);
        fma2(acc2[3][0], a23.y, b2.x); fma2(acc2[3][1], a23.y, b2.y);
        fma2(acc2[4][0], a45.x, b2.x); fma2(acc2[4][1], a45.x, b2.y);
        fma2(acc2[5][0], a45.y, b2.x); fma2(acc2[5][1], a45.y, b2.y);
        fma2(acc2[6][0], a67.x, b2.x); fma2(acc2[6][1], a67.x, b2.y);
        fma2(acc2[7][0], a67.y, b2.x); fma2(acc2[7][1], a67.y, b2.y);
    }

    #pragma unroll
    for (int i = 0; i < 8; i++) {
        float2 p0 = unpack2(acc2[i][0]);
        float2 p1 = unpack2(acc2[i][1]);
        float accv[4] = {p0.x, p0.y, p1.x, p1.y};
        #pragma unroll
        for (int j = 0; j < 4; j++) {
            int r = bm + tm + i;
            int c = bn + tn + j;
            float v = accv[j] + bias[c];
            if (mode == MODE_Q) {
                int b = r >> 11, s = r & 2047, h = c >> 6, dh = c & 63;
                g_Q[(((size_t)b * H_ + h) * S_ + s) * DH_ + dh] = v;
            } else if (mode == MODE_K) {
                int b = r >> 11, s = r & 2047, h = c >> 6, dh = c & 63;
                g_Kt[(((size_t)b * H_ + h) * DH_ + dh) * S_ + s] = v;
            } else if (mode == MODE_V) {
                g_V[(size_t)r * DH_ + c] = v;
            } else {
                out[(size_t)r * D_ + c] = v;
            }
        }
    }
}

// Fused Q/K/V projection + out_avg zeroing.
// gridDim = (M/128, D/64, 3); z selects mode. The 224 idle V-slots
// (mode==V, blockIdx.y>0) zero out_avg instead of exiting, replacing
// the serial cudaMemsetAsync node (overlaps with GEMM compute; the
// kernel boundary orders it before attn's atomic accumulation).
__global__ __launch_bounds__(256, 2) void qkv_kernel(
    const float* __restrict__ x,
    const float* __restrict__ Wq, const float* __restrict__ bq,
    const float* __restrict__ Wk, const float* __restrict__ bk,
    const float* __restrict__ Wv, const float* __restrict__ bv,
    float* __restrict__ out_avg)
{
    int mode = blockIdx.z;
    if (mode == MODE_Q) {
        gemm_tile(x, Wq, bq, nullptr, D_, D_, MODE_Q, blockIdx.x, blockIdx.y);
    } else if (mode == MODE_K) {
        gemm_tile(x, Wk, bk, nullptr, D_, D_, MODE_K, blockIdx.x, blockIdx.y);
    } else if (blockIdx.y == 0) {
        gemm_tile(x, Wv, bv, nullptr, D_, DH_, MODE_V, blockIdx.x, 0);
    } else {
        // idle V-slot: zero a slice of out_avg (B*S*S floats)
        const size_t total4 = (size_t)B_ * S_ * S_ / 4;     // float4 count
        int zblk = blockIdx.x * 7 + (blockIdx.y - 1);       // 0..223
        size_t idx = (size_t)zblk * 256 + threadIdx.x;
        const size_t stride = 224u * 256u;
        float4 zv = {0.f, 0.f, 0.f, 0.f};
        float4* avg4 = (float4*)out_avg;
        for (size_t i = idx; i < total4; i += stride) avg4[i] = zv;
    }
}

// Output projection: heads @ Wout + bout -> out_x
__global__ __launch_bounds__(256, 2) void out_kernel(
    const float* __restrict__ Wout, const float* __restrict__ bout,
    float* __restrict__ out_x)
{
    gemm_tile(g_heads, Wout, bout, out_x, D_, D_, MODE_OUT, blockIdx.x, blockIdx.y);
}

// ------------------------------------------------------------------
// Fused attention, persistent grid over (item, head) units:
// 2048 units / 148 blocks -> 13-14 units each (~0.5% imbalance).
// 512 threads, warp w owns q row w. out_avg pre-zeroed by qkv_kernel;
// cross-block head accumulation into avg rows is atomic (REDG).
// Logits loop is SOFTWARE-PIPELINED: K load for d+1 issues before
// the FFMA2 burst for d (per-warp MLP=2, hides L2 latency).
// ------------------------------------------------------------------
#define TQ 16
#define NTHR 512
#define NPERS 148                       // persistent blocks (= SM count)
#define NUNITS (B_ * (S_ / TQ) * H_)    // 2048 (item, head) units
#define CAP 192                         // candidate list capacity per warp
#define CPL (CAP / 32)                  // candidates per lane in registers
#define LG_FLOATS   (TQ * S_)
#define QST_FLOATS  (64 * TQ)
#define ATTN_SMEM ((LG_FLOATS + QST_FLOATS + TQ * CAP) * 4)

__global__ __launch_bounds__(NTHR, 1) void attn_kernel(float* __restrict__ out_avg)
{
    extern __shared__ float sm[];
    float* lg   = sm;                            // [TQ][S_] logits
    float* qsT  = sm + LG_FLOATS;                // [64][TQ] q transposed
    int*   lists = (int*)(sm + LG_FLOATS + QST_FLOATS);  // [TQ][CAP]

    int tid  = threadIdx.x;
    int w    = tid >> 5;           // 0..15 : warp == q row
    int lane = tid & 31;
    unsigned lmlt = (1u << lane) - 1u;

    for (int unit = blockIdx.x; unit < NUNITS; unit += NPERS) {
        int h    = unit & (H_ - 1);      // head
        int item = unit >> 3;            // (batch, q-tile)
        int b    = item >> 7;
        int s0   = (item & 127) * TQ;

        // ---- load q tile transposed ----
        for (int idx = tid; idx < 64 * TQ; idx += NTHR) {
            int q = idx >> 6, d = idx & 63;
            qsT[d * TQ + q] = g_Q[(((size_t)b * H_ + h) * S_ + s0 + q) * DH_ + d];
        }
        __syncthreads();

        // ---- logits: each thread owns 4 contiguous keys (512*4 = 2048) ----
        const float* KtH = g_Kt + ((size_t)b * H_ + h) * DH_ * S_;
        {
            int jb = 4 * tid;
            unsigned long long acc2[4][TQ / 2] = {};  // [key u][q-pair]

            float4 kd = *(const float4*)&KtH[jb];     // prefetch d = 0
            #pragma unroll 2
            for (int d = 0; d < 64; d++) {
                // prefetch next iteration's K row FIRST (MLP = 2)
                float4 kd_n;
                if (d + 1 < 64)
                    kd_n = *(const float4*)&KtH[(size_t)(d + 1) * S_ + jb];
                unsigned long long kk2[4] = {
                    pack2(kd.x, kd.x), pack2(kd.y, kd.y),
                    pack2(kd.z, kd.z), pack2(kd.w, kd.w)
                };
                const ulonglong2* qrow = (const ulonglong2*)&qsT[d * TQ];
                #pragma unroll
                for (int qv = 0; qv < TQ / 4; qv++) {
                    ulonglong2 qp = qrow[qv];                          // LDS.128 broadcast
                    #pragma unroll
                    for (int u = 0; u < 4; u++) {
                        fma2(acc2[u][2 * qv + 0], kk2[u], qp.x);
                        fma2(acc2[u][2 * qv + 1], kk2[u], qp.y);
                    }
                }
                kd = kd_n;
            }
            #pragma unroll
            for (int q2 = 0; q2 < TQ / 2; q2++) {
                float2 p0 = unpack2(acc2[0][q2]);
                float2 p1 = unpack2(acc2[1][q2]);
                float2 p2 = unpack2(acc2[2][q2]);
                float2 p3 = unpack2(acc2[3][q2]);
                float4 e = {p0.x, p1.x, p2.x, p3.x};
                float4 o = {p0.y, p1.y, p2.y, p3.y};
                *(float4*)&lg[(2 * q2 + 0) * S_ + jb] = e;  // STS.128
                *(float4*)&lg[(2 * q2 + 1) * S_ + jb] = o;  // STS.128
            }
        }
        __syncthreads();

        // ---- sparsemax, warp w owns row w ----
        float* z = lg + w * S_;
        const float4* z4 = (const float4*)z;
        int* list = lists + w * CAP;

        // pass A: row max
        float m = -1e30f;
        #pragma unroll
        for (int i = 0; i < 16; i++) {
            float4 v = z4[lane + 32 * i];
            m = fmaxf(m, fmaxf(fmaxf(v.x, v.y), fmaxf(v.z, v.w)));
        }
        #pragma unroll
        for (int o = 16; o; o >>= 1) m = fmaxf(m, __shfl_xor_sync(0xffffffffu, m, o));
        float thr = m - 1.0f;

        // pass B: gather candidate indices (z > thr), warp-compacted
        int cnt = 0;
        bool ovf = false;
        #pragma unroll
        for (int i = 0; i < 16; i++) {
            float4 v = z4[lane + 32 * i];
            int ebase = 4 * (lane + 32 * i);
            float vals[4] = {v.x, v.y, v.z, v.w};
            #pragma unroll
            for (int comp = 0; comp < 4; comp++) {
                bool c = vals[comp] > thr;
                unsigned bal = __ballot_sync(0xffffffffu, c);
                int n = __popc(bal);
                if (cnt + n > CAP) { ovf = true; }
                else if (c) list[cnt + __popc(bal & lmlt)] = ebase + comp;
                cnt += n;
            }
        }

        float tau;
        if (!ovf) {
            // candidates -> registers
            float cv[CPL];
            int my_n = 0;
            for (int c = lane; c < cnt; c += 32) {
                cv[my_n] = z[list[c]];
                my_n++;
            }
            // Michelot restricted to candidates (superset of support)
            tau = thr;
            int cprev = -1;
            for (int it = 0; it < 48; it++) {
                float s = 0.f; int c = 0;
                #pragma unroll
                for (int k = 0; k < CPL; k++) {
                    if (k < my_n && cv[k] > tau) { s += cv[k]; c++; }
                }
                #pragma unroll
                for (int o = 16; o; o >>= 1) {
                    s += __shfl_xor_sync(0xffffffffu, s, o);
                    c += __shfl_xor_sync(0xffffffffu, c, o);
                }
                if (c == 0) break;
                tau = (s - 1.0f) / (float)c;
                if (c == cprev) break;
                cprev = c;
            }
        } else {
            // fallback: full-scan Michelot
            float ssum = 0.f;
            #pragma unroll
            for (int i = 0; i < 16; i++) {
                float4 v = z4[lane + 32 * i];
                ssum += (v.x + v.y) + (v.z + v.w);
            }
            #pragma unroll
            for (int o = 16; o; o >>= 1) ssum += __shfl_xor_sync(0xffffffffu, ssum, o);
            tau = (ssum - 1.0f) * (1.0f / (float)S_);
            int cprev = S_;
            for (int it = 0; it < 64; it++) {
                float s = 0.f; int c = 0;
                #pragma unroll
                for (int i = 0; i < 16; i++) {
                    float4 v = z4[lane + 32 * i];
                    if (v.x > tau) { s += v.x; c++; }
                    if (v.y > tau) { s += v.y; c++; }
                    if (v.z > tau) { s += v.z; c++; }
                    if (v.w > tau) { s += v.w; c++; }
                }
                #pragma unroll
                for (int o = 16; o; o >>= 1) {
                    s += __shfl_xor_sync(0xffffffffu, s, o);
                    c += __shfl_xor_sync(0xffffffffu, c, o);
                }
                if (c == 0) break;
                tau = (s - 1.0f) / (float)c;
                if (c == cprev) break;
                cprev = c;
            }
        }

        // ---- sparse PV + avg_attention over support (REDG adds) ----
        float* avg_row = out_avg + ((size_t)b * S_ + s0 + w) * S_;
        const float* Vb = g_V + (size_t)b * S_ * DH_;
        float a0 = 0.f, a1 = 0.f;

        if (!ovf) {
            for (int c = 0; c < cnt; c++) {
                int idx = list[c];               // LDS broadcast
                float p = z[idx] - tau;          // LDS broadcast (uniform)
                if (p > 0.f) {
                    if (lane == 0) atomicAdd(&avg_row[idx], 0.125f * p);  // -> REDG
                    const float* vr = Vb + (size_t)idx * DH_;
                    a0 += p * vr[lane];
                    a1 += p * vr[lane + 32];
                }
            }
        } else {
            for (int i = 0; i < 64; i++) {
                int j = i * 32 + lane;
                float p = z[j] - tau;
                bool nz = p > 0.0f;
                unsigned mm = __ballot_sync(0xffffffffu, nz);
                if (nz) atomicAdd(&avg_row[j], 0.125f * p);               // -> REDG
                while (mm) {
                    int src = __ffs(mm) - 1;
                    mm &= mm - 1;
                    float pb = __shfl_sync(0xffffffffu, p, src);
                    const float* vr = Vb + (size_t)(i * 32 + src) * DH_;
                    a0 += pb * vr[lane];
                    a1 += pb * vr[lane + 32];
                }
            }
        }

        size_t ho = ((size_t)b * S_ + s0 + w) * D_ + h * DH_;
        g_heads[ho + lane]      = a0;
        g_heads[ho + lane + 32] = a1;
        __syncthreads();
    }
}

// ------------------------------------------------------------------
extern "C" void kernel_launch(void* const* d_in, const int* in_sizes, int n_in,
                              void* d_out, int out_size)
{
    const float* x    = (const float*)d_in[0];
    const float* Wq   = (const float*)d_in[1];
    const float* bq   = (const float*)d_in[2];
    const float* Wk   = (const float*)d_in[3];
    const float* bk   = (const float*)d_in[4];
    const float* Wv   = (const float*)d_in[5];
    const float* bv   = (const float*)d_in[6];
    const float* Wout = (const float*)d_in[7];
    const float* bout = (const float*)d_in[8];

    float* out_x   = (float*)d_out;
    float* out_avg = out_x + (size_t)B_ * S_ * D_;

    const int M = B_ * S_;                       // 4096
    dim3 blk(256);

    // fused Q/K/V projection + out_avg zeroing: one launch
    qkv_kernel<<<dim3(M / 128, D_ / 64, 3), blk>>>(x, Wq, bq, Wk, bk, Wv, bv, out_avg);

    // attention over (item, head) units
    cudaFuncSetAttribute(attn_kernel, cudaFuncAttributeMaxDynamicSharedMemorySize, ATTN_SMEM);
    attn_kernel<<<dim3(NPERS, 1), dim3(NTHR), ATTN_SMEM>>>(out_avg);

    out_kernel<<<dim3(M / 128, D_ / 64), blk>>>(Wout, bout, out_x);
}

// round 17
// speedup vs baseline: 1.0218x; 1.0218x over previous
#include <cuda_runtime.h>
#include <cstdint>

#define B_  2
#define S_  2048
#define D_  512
#define H_  8
#define DH_ 64

// ---- scratch (allocation-free: __device__ globals) ----
__device__ float g_Q [(size_t)B_ * H_ * S_ * DH_];   // [B][H][S][DH]   8 MB
__device__ float g_Kt[(size_t)B_ * H_ * DH_ * S_];   // [B][H][DH][S]   8 MB
__device__ float g_V [(size_t)B_ * S_ * DH_];        // [B][S][DH]      1 MB
__device__ float g_heads[(size_t)B_ * S_ * D_];      // [B][S][D]       8 MB

#define MODE_Q   0
#define MODE_K   1
#define MODE_V   2
#define MODE_OUT 3

// ---- packed fp32x2 helpers (sm_10x) ----
__device__ __forceinline__ void fma2(unsigned long long& d,
                                     unsigned long long a,
                                     unsigned long long b) {
    asm("fma.rn.f32x2 %0, %1, %2, %0;" : "+l"(d) : "l"(a), "l"(b));
}
__device__ __forceinline__ unsigned long long pack2(float x, float y) {
    unsigned long long r;
    asm("mov.b64 %0, {%1, %2};" : "=l"(r) : "f"(x), "f"(y));
    return r;
}
__device__ __forceinline__ float2 unpack2(unsigned long long v) {
    float2 r;
    asm("mov.b64 {%0, %1}, %2;" : "=f"(r.x), "=f"(r.y) : "l"(v));
    return r;
}

// ------------------------------------------------------------------
// GEMM tile body (v2, L1-wavefront optimized per R15 ncu):
// C = A[M x K] @ W[K x N] + bias, scatter per mode.
// BM=128, BN=64, BK=32, 256 threads, microtile 8m x 4n.
// f32 smem (A rows padded to 132 floats), accumulators packed over M:
// A-pairs come NATIVE from LDS.128 (no dup movs); 4 B-dup movs/kk.
// Per kk: 3 LDS.128 (4 wf) + 4 movs + 16 FFMA2 (32 MACs) = 23 issues.
// A global staging is line-coalesced (full 128B rows per warp-inst).
// Double-buffered, one __syncthreads per 32-k tile.
// ------------------------------------------------------------------
#define AROW 132                         // padded A row (floats), 16B-aligned
#define GEMM_SMEM ((2*32*AROW + 2*32*64) * 4)   // 50176 bytes

__device__ __forceinline__ void gemm_tile(
    const float* __restrict__ A, const float* __restrict__ W,
    const float* __restrict__ bias, float* __restrict__ out,
    int K, int N, int mode, int bxm, int bxn)
{
    extern __shared__ float gsm[];
    float* As = gsm;                     // [2][32][AROW]
    float* Bs = gsm + 2 * 32 * AROW;     // [2][32][64]

    int t  = threadIdx.x;
    int bm = bxm * 128;
    int bn = bxn * 64;
    int tm = (t >> 4) * 8;               // 16 groups x 8 rows = 128
    int tn = (t & 15) * 4;

    // A staging map: thread covers rows ar+j*32 (j=0..3), k-cols aq..aq+3
    int ar = t >> 3;                     // 0..31
    int aq = (t & 7) * 4;                // 0,4,...,28
    // B staging map: thread covers k-rows kb+j*16 (j=0..1), n-cols bn4..bn4+3
    int kb  = t >> 4;                    // 0..15
    int bn4 = (t & 15) * 4;

    unsigned long long acc2[4][4] = {};  // [m-pair i][n] ; rows tm+2i, tm+2i+1

    // ---- prologue: stage tile 0 into buffer 0 ----
    {
        float4 av[4], bv[2];
        #pragma unroll
        for (int j = 0; j < 4; j++)
            av[j] = *(const float4*)&A[(size_t)(bm + ar + j * 32) * K + aq];
        #pragma unroll
        for (int j = 0; j < 2; j++)
            bv[j] = *(const float4*)&W[(size_t)(kb + j * 16) * N + bn + bn4];
        #pragma unroll
        for (int j = 0; j < 4; j++) {
            float* dst = &As[(aq + 0) * AROW + (ar + j * 32)];
            dst[0 * AROW] = av[j].x;
            dst[1 * AROW] = av[j].y;
            dst[2 * AROW] = av[j].z;
            dst[3 * AROW] = av[j].w;
        }
        #pragma unroll
        for (int j = 0; j < 2; j++)
            *(float4*)&Bs[(kb + j * 16) * 64 + bn4] = bv[j];
    }
    __syncthreads();

    int cur = 0;
    for (int k0 = 32; k0 < K; k0 += 32, cur ^= 1) {
        // prefetch next tile's global loads FIRST (overlap with compute)
        float4 av[4], bv[2];
        #pragma unroll
        for (int j = 0; j < 4; j++)
            av[j] = *(const float4*)&A[(size_t)(bm + ar + j * 32) * K + k0 + aq];
        #pragma unroll
        for (int j = 0; j < 2; j++)
            bv[j] = *(const float4*)&W[(size_t)(k0 + kb + j * 16) * N + bn + bn4];

        // compute current tile
        const float* Ac = As + cur * 32 * AROW;
        const float* Bc = Bs + cur * 32 * 64;
        #pragma unroll 8
        for (int kk = 0; kk < 32; kk++) {
            ulonglong2 ap0 = *(const ulonglong2*)&Ac[kk * AROW + tm];     // pairs (m0,m1),(m2,m3)
            ulonglong2 ap1 = *(const ulonglong2*)&Ac[kk * AROW + tm + 4]; // pairs (m4,m5),(m6,m7)
            float4 b = *(const float4*)&Bc[kk * 64 + tn];
            unsigned long long bd0 = pack2(b.x, b.x);
            unsigned long long bd1 = pack2(b.y, b.y);
            unsigned long long bd2 = pack2(b.z, b.z);
            unsigned long long bd3 = pack2(b.w, b.w);
            fma2(acc2[0][0], ap0.x, bd0); fma2(acc2[0][1], ap0.x, bd1);
            fma2(acc2[0][2], ap0.x, bd2); fma2(acc2[0][3], ap0.x, bd3);
            fma2(acc2[1][0], ap0.y, bd0); fma2(acc2[1][1], ap0.y, bd1);
            fma2(acc2[1][2], ap0.y, bd2); fma2(acc2[1][3], ap0.y, bd3);
            fma2(acc2[2][0], ap1.x, bd0); fma2(acc2[2][1], ap1.x, bd1);
            fma2(acc2[2][2], ap1.x, bd2); fma2(acc2[2][3], ap1.x, bd3);
            fma2(acc2[3][0], ap1.y, bd0); fma2(acc2[3][1], ap1.y, bd1);
            fma2(acc2[3][2], ap1.y, bd2); fma2(acc2[3][3], ap1.y, bd3);
        }

        // stage next tile into the other buffer
        int nxt = cur ^ 1;
        float* An = As + nxt * 32 * AROW;
        float* Bn = Bs + nxt * 32 * 64;
        #pragma unroll
        for (int j = 0; j < 4; j++) {
            float* dst = &An[(aq + 0) * AROW + (ar + j * 32)];
            dst[0 * AROW] = av[j].x;
            dst[1 * AROW] = av[j].y;
            dst[2 * AROW] = av[j].z;
            dst[3 * AROW] = av[j].w;
        }
        #pragma unroll
        for (int j = 0; j < 2; j++)
            *(float4*)&Bn[(kb + j * 16) * 64 + bn4] = bv[j];
        __syncthreads();
    }

    // ---- epilogue: compute last tile ----
    {
        const float* Ac = As + cur * 32 * AROW;
        const float* Bc = Bs + cur * 32 * 64;
        #pragma unroll 8
        for (int kk = 0; kk < 32; kk++) {
            ulonglong2 ap0 = *(const ulonglong2*)&Ac[kk * AROW + tm];
            ulonglong2 ap1 = *(const ulonglong2*)&Ac[kk * AROW + tm + 4];
            float4 b = *(const float4*)&Bc[kk * 64 + tn];
            unsigned long long bd0 = pack2(b.x, b.x);
            unsigned long long bd1 = pack2(b.y, b.y);
            unsigned long long bd2 = pack2(b.z, b.z);
            unsigned long long bd3 = pack2(b.w, b.w);
            fma2(acc2[0][0], ap0.x, bd0); fma2(acc2[0][1], ap0.x, bd1);
            fma2(acc2[0][2], ap0.x, bd2); fma2(acc2[0][3], ap0.x, bd3);
            fma2(acc2[1][0], ap0.y, bd0); fma2(acc2[1][1], ap0.y, bd1);
            fma2(acc2[1][2], ap0.y, bd2); fma2(acc2[1][3], ap0.y, bd3);
            fma2(acc2[2][0], ap1.x, bd0); fma2(acc2[2][1], ap1.x, bd1);
            fma2(acc2[2][2], ap1.x, bd2); fma2(acc2[2][3], ap1.x, bd3);
            fma2(acc2[3][0], ap1.y, bd0); fma2(acc2[3][1], ap1.y, bd1);
            fma2(acc2[3][2], ap1.y, bd2); fma2(acc2[3][3], ap1.y, bd3);
        }
    }

    // ---- writeback: acc2[i][n] holds rows (tm+2i, tm+2i+1), col tn+n ----
    #pragma unroll
    for (int i = 0; i < 4; i++) {
        #pragma unroll
        for (int n = 0; n < 4; n++) {
            float2 p = unpack2(acc2[i][n]);
            int c = bn + tn + n;
            float bb = bias[c];
            #pragma unroll
            for (int half = 0; half < 2; half++) {
                int r = bm + tm + 2 * i + half;
                float v = (half ? p.y : p.x) + bb;
                if (mode == MODE_Q) {
                    int b = r >> 11, s = r & 2047, h = c >> 6, dh = c & 63;
                    g_Q[(((size_t)b * H_ + h) * S_ + s) * DH_ + dh] = v;
                } else if (mode == MODE_K) {
                    int b = r >> 11, s = r & 2047, h = c >> 6, dh = c & 63;
                    g_Kt[(((size_t)b * H_ + h) * DH_ + dh) * S_ + s] = v;
                } else if (mode == MODE_V) {
                    g_V[(size_t)r * DH_ + c] = v;
                } else {
                    out[(size_t)r * D_ + c] = v;
                }
            }
        }
    }
}

// Fused Q/K/V projection + out_avg zeroing.
// gridDim = (M/128, D/64, 3); z selects mode. The 224 idle V-slots
// (mode==V, blockIdx.y>0) zero out_avg instead of exiting.
__global__ __launch_bounds__(256, 2) void qkv_kernel(
    const float* __restrict__ x,
    const float* __restrict__ Wq, const float* __restrict__ bq,
    const float* __restrict__ Wk, const float* __restrict__ bk,
    const float* __restrict__ Wv, const float* __restrict__ bv,
    float* __restrict__ out_avg)
{
    int mode = blockIdx.z;
    if (mode == MODE_Q) {
        gemm_tile(x, Wq, bq, nullptr, D_, D_, MODE_Q, blockIdx.x, blockIdx.y);
    } else if (mode == MODE_K) {
        gemm_tile(x, Wk, bk, nullptr, D_, D_, MODE_K, blockIdx.x, blockIdx.y);
    } else if (blockIdx.y == 0) {
        gemm_tile(x, Wv, bv, nullptr, D_, DH_, MODE_V, blockIdx.x, 0);
    } else {
        // idle V-slot: zero a slice of out_avg (B*S*S floats)
        const size_t total4 = (size_t)B_ * S_ * S_ / 4;     // float4 count
        int zblk = blockIdx.x * 7 + (blockIdx.y - 1);       // 0..223
        size_t idx = (size_t)zblk * 256 + threadIdx.x;
        const size_t stride = 224u * 256u;
        float4 zv = {0.f, 0.f, 0.f, 0.f};
        float4* avg4 = (float4*)out_avg;
        for (size_t i = idx; i < total4; i += stride) avg4[i] = zv;
    }
}

// Output projection: heads @ Wout + bout -> out_x
__global__ __launch_bounds__(256, 2) void out_kernel(
    const float* __restrict__ Wout, const float* __restrict__ bout,
    float* __restrict__ out_x)
{
    gemm_tile(g_heads, Wout, bout, out_x, D_, D_, MODE_OUT, blockIdx.x, blockIdx.y);
}

// ------------------------------------------------------------------
// Fused attention, persistent grid over (item, head) units:
// 2048 units / 148 blocks. 512 threads, warp w owns q row w.
// out_avg pre-zeroed by qkv_kernel; avg adds are atomic (REDG).
// Logits loop software-pipelined 2 deep (per-warp MLP=3).
// ------------------------------------------------------------------
#define TQ 16
#define NTHR 512
#define NPERS 148                       // persistent blocks (= SM count)
#define NUNITS (B_ * (S_ / TQ) * H_)    // 2048 (item, head) units
#define CAP 192                         // candidate list capacity per warp
#define CPL (CAP / 32)                  // candidates per lane in registers
#define LG_FLOATS   (TQ * S_)
#define QST_FLOATS  (64 * TQ)
#define ATTN_SMEM ((LG_FLOATS + QST_FLOATS + TQ * CAP) * 4)

__global__ __launch_bounds__(NTHR, 1) void attn_kernel(float* __restrict__ out_avg)
{
    extern __shared__ float sm[];
    float* lg   = sm;                            // [TQ][S_] logits
    float* qsT  = sm + LG_FLOATS;                // [64][TQ] q transposed
    int*   lists = (int*)(sm + LG_FLOATS + QST_FLOATS);  // [TQ][CAP]

    int tid  = threadIdx.x;
    int w    = tid >> 5;           // 0..15 : warp == q row
    int lane = tid & 31;
    unsigned lmlt = (1u << lane) - 1u;

    for (int unit = blockIdx.x; unit < NUNITS; unit += NPERS) {
        int h    = unit & (H_ - 1);      // head
        int item = unit >> 3;            // (batch, q-tile)
        int b    = item >> 7;
        int s0   = (item & 127) * TQ;

        // ---- load q tile transposed ----
        for (int idx = tid; idx < 64 * TQ; idx += NTHR) {
            int q = idx >> 6, d = idx & 63;
            qsT[d * TQ + q] = g_Q[(((size_t)b * H_ + h) * S_ + s0 + q) * DH_ + d];
        }
        __syncthreads();

        // ---- logits: each thread owns 4 contiguous keys (512*4 = 2048) ----
        const float* KtH = g_Kt + ((size_t)b * H_ + h) * DH_ * S_;
        {
            int jb = 4 * tid;
            unsigned long long acc2[4][TQ / 2] = {};  // [key u][q-pair]

            float4 kd0 = *(const float4*)&KtH[jb];              // d = 0
            float4 kd1 = *(const float4*)&KtH[(size_t)S_ + jb]; // d = 1
            #pragma unroll 2
            for (int d = 0; d < 64; d++) {
                // prefetch d+2 FIRST (per-warp MLP = 3)
                float4 kd2;
                if (d + 2 < 64)
                    kd2 = *(const float4*)&KtH[(size_t)(d + 2) * S_ + jb];
                unsigned long long kk2[4] = {
                    pack2(kd0.x, kd0.x), pack2(kd0.y, kd0.y),
                    pack2(kd0.z, kd0.z), pack2(kd0.w, kd0.w)
                };
                const ulonglong2* qrow = (const ulonglong2*)&qsT[d * TQ];
                #pragma unroll
                for (int qv = 0; qv < TQ / 4; qv++) {
                    ulonglong2 qp = qrow[qv];                   // LDS.128 broadcast
                    #pragma unroll
                    for (int u = 0; u < 4; u++) {
                        fma2(acc2[u][2 * qv + 0], kk2[u], qp.x);
                        fma2(acc2[u][2 * qv + 1], kk2[u], qp.y);
                    }
                }
                kd0 = kd1;
                kd1 = kd2;
            }
            #pragma unroll
            for (int q2 = 0; q2 < TQ / 2; q2++) {
                float2 p0 = unpack2(acc2[0][q2]);
                float2 p1 = unpack2(acc2[1][q2]);
                float2 p2 = unpack2(acc2[2][q2]);
                float2 p3 = unpack2(acc2[3][q2]);
                float4 e = {p0.x, p1.x, p2.x, p3.x};
                float4 o = {p0.y, p1.y, p2.y, p3.y};
                *(float4*)&lg[(2 * q2 + 0) * S_ + jb] = e;  // STS.128
                *(float4*)&lg[(2 * q2 + 1) * S_ + jb] = o;  // STS.128
            }
        }
        __syncthreads();

        // ---- sparsemax, warp w owns row w ----
        float* z = lg + w * S_;
        const float4* z4 = (const float4*)z;
        int* list = lists + w * CAP;

        // pass A: row max
        float m = -1e30f;
        #pragma unroll
        for (int i = 0; i < 16; i++) {
            float4 v = z4[lane + 32 * i];
            m = fmaxf(m, fmaxf(fmaxf(v.x, v.y), fmaxf(v.z, v.w)));
        }
        #pragma unroll
        for (int o = 16; o; o >>= 1) m = fmaxf(m, __shfl_xor_sync(0xffffffffu, m, o));
        float thr = m - 1.0f;

        // pass B: gather candidate indices (z > thr), warp-compacted
        int cnt = 0;
        bool ovf = false;
        #pragma unroll
        for (int i = 0; i < 16; i++) {
            float4 v = z4[lane + 32 * i];
            int ebase = 4 * (lane + 32 * i);
            float vals[4] = {v.x, v.y, v.z, v.w};
            #pragma unroll
            for (int comp = 0; comp < 4; comp++) {
                bool c = vals[comp] > thr;
                unsigned bal = __ballot_sync(0xffffffffu, c);
                int n = __popc(bal);
                if (cnt + n > CAP) { ovf = true; }
                else if (c) list[cnt + __popc(bal & lmlt)] = ebase + comp;
                cnt += n;
            }
        }

        float tau;
        if (!ovf) {
            // candidates -> registers
            float cv[CPL];
            int my_n = 0;
            for (int c = lane; c < cnt; c += 32) {
                cv[my_n] = z[list[c]];
                my_n++;
            }
            // Michelot restricted to candidates (superset of support)
            tau = thr;
            int cprev = -1;
            for (int it = 0; it < 48; it++) {
                float s = 0.f; int c = 0;
                #pragma unroll
                for (int k = 0; k < CPL; k++) {
                    if (k < my_n && cv[k] > tau) { s += cv[k]; c++; }
                }
                #pragma unroll
                for (int o = 16; o; o >>= 1) {
                    s += __shfl_xor_sync(0xffffffffu, s, o);
                    c += __shfl_xor_sync(0xffffffffu, c, o);
                }
                if (c == 0) break;
                tau = (s - 1.0f) / (float)c;
                if (c == cprev) break;
                cprev = c;
            }
        } else {
            // fallback: full-scan Michelot
            float ssum = 0.f;
            #pragma unroll
            for (int i = 0; i < 16; i++) {
                float4 v = z4[lane + 32 * i];
                ssum += (v.x + v.y) + (v.z + v.w);
            }
            #pragma unroll
            for (int o = 16; o; o >>= 1) ssum += __shfl_xor_sync(0xffffffffu, ssum, o);
            tau = (ssum - 1.0f) * (1.0f / (float)S_);
            int cprev = S_;
            for (int it = 0; it < 64; it++) {
                float s = 0.f; int c = 0;
                #pragma unroll
                for (int i = 0; i < 16; i++) {
                    float4 v = z4[lane + 32 * i];
                    if (v.x > tau) { s += v.x; c++; }
                    if (v.y > tau) { s += v.y; c++; }
                    if (v.z > tau) { s += v.z; c++; }
                    if (v.w > tau) { s += v.w; c++; }
                }
                #pragma unroll
                for (int o = 16; o; o >>= 1) {
                    s += __shfl_xor_sync(0xffffffffu, s, o);
                    c += __shfl_xor_sync(0xffffffffu, c, o);
                }
                if (c == 0) break;
                tau = (s - 1.0f) / (float)c;
                if (c == cprev) break;
                cprev = c;
            }
        }

        // ---- sparse PV + avg_attention over support (REDG adds) ----
        float* avg_row = out_avg + ((size_t)b * S_ + s0 + w) * S_;
        const float* Vb = g_V + (size_t)b * S_ * DH_;
        float a0 = 0.f, a1 = 0.f;

        if (!ovf) {
            for (int c = 0; c < cnt; c++) {
                int idx = list[c];               // LDS broadcast
                float p = z[idx] - tau;          // LDS broadcast (uniform)
                if (p > 0.f) {
                    if (lane == 0) atomicAdd(&avg_row[idx], 0.125f * p);  // -> REDG
                    const float* vr = Vb + (size_t)idx * DH_;
                    a0 += p * vr[lane];
                    a1 += p * vr[lane + 32];
                }
            }
        } else {
            for (int i = 0; i < 64; i++) {
                int j = i * 32 + lane;
                float p = z[j] - tau;
                bool nz = p > 0.0f;
                unsigned mm = __ballot_sync(0xffffffffu, nz);
                if (nz) atomicAdd(&avg_row[j], 0.125f * p);               // -> REDG
                while (mm) {
                    int src = __ffs(mm) - 1;
                    mm &= mm - 1;
                    float pb = __shfl_sync(0xffffffffu, p, src);
                    const float* vr = Vb + (size_t)(i * 32 + src) * DH_;
                    a0 += pb * vr[lane];
                    a1 += pb * vr[lane + 32];
                }
            }
        }

        size_t ho = ((size_t)b * S_ + s0 + w) * D_ + h * DH_;
        g_heads[ho + lane]      = a0;
        g_heads[ho + lane + 32] = a1;
        __syncthreads();
    }
}

// ------------------------------------------------------------------
extern "C" void kernel_launch(void* const* d_in, const int* in_sizes, int n_in,
                              void* d_out, int out_size)
{
    const float* x    = (const float*)d_in[0];
    const float* Wq   = (const float*)d_in[1];
    const float* bq   = (const float*)d_in[2];
    const float* Wk   = (const float*)d_in[3];
    const float* bk   = (const float*)d_in[4];
    const float* Wv   = (const float*)d_in[5];
    const float* bv   = (const float*)d_in[6];
    const float* Wout = (const float*)d_in[7];
    const float* bout = (const float*)d_in[8];

    float* out_x   = (float*)d_out;
    float* out_avg = out_x + (size_t)B_ * S_ * D_;

    const int M = B_ * S_;                       // 4096
    dim3 blk(256);

    cudaFuncSetAttribute(qkv_kernel, cudaFuncAttributeMaxDynamicSharedMemorySize, GEMM_SMEM);
    cudaFuncSetAttribute(out_kernel, cudaFuncAttributeMaxDynamicSharedMemorySize, GEMM_SMEM);
    cudaFuncSetAttribute(attn_kernel, cudaFuncAttributeMaxDynamicSharedMemorySize, ATTN_SMEM);

    // fused Q/K/V projection + out_avg zeroing: one launch
    qkv_kernel<<<dim3(M / 128, D_ / 64, 3), blk, GEMM_SMEM>>>(x, Wq, bq, Wk, bk, Wv, bv, out_avg);

    // attention over (item, head) units
    attn_kernel<<<dim3(NPERS, 1), dim3(NTHR), ATTN_SMEM>>>(out_avg);

    out_kernel<<<dim3(M / 128, D_ / 64), blk, GEMM_SMEM>>>(Wout, bout, out_x);
}